// round 1
// baseline (speedup 1.0000x reference)
#include <cuda_runtime.h>
#include <math.h>

// Problem constants
#define SIG_LEN   131072
#define BATCH     64
#define NW        4
#define ROWS      (BATCH * NW)        // 256
#define T_OUT     131166              // per-row output length
// Level output lengths: L[i] = (L[i-1] + 14)/2 + 1
// 131072 -> 65544 -> 32780 -> 16398 -> 8207 -> 4111 -> 2063

// Scratch ping-pong buffers (device globals: allocation-free per harness rules)
__device__ float g_bufA[(size_t)ROWS * 65544];   // levels 1,3,5 approx
__device__ float g_bufB[(size_t)ROWS * 32780];   // levels 2,4 approx
__device__ float g_filt[2][4][16];               // [lp/hp][wavelet][tap]

// ---------------------------------------------------------------------------
// Filter constraint: pad->rfft(64)->gaussian weight->irfft->trunc(16)->norm*sqrt2
// Linear map on the 16 taps; cos table has only 64 distinct values.
// ---------------------------------------------------------------------------
__global__ void constrain_kernel(const float* __restrict__ low,
                                 const float* __restrict__ high) {
    __shared__ double ctab[64];
    __shared__ double vals[128];
    const int tid = threadIdx.x;                 // 0..127
    if (tid < 64) ctab[tid] = cos(2.0 * M_PI * (double)tid / 64.0);
    __syncthreads();

    const int bank = tid >> 6;                   // 0 = lp, 1 = hp
    const int n    = (tid >> 4) & 3;             // wavelet
    const int j    = tid & 15;                   // output tap
    const float* src = bank ? high : low;

    const double target = ((double)n + 0.5) / (double)NW * 0.5 + (bank ? 0.5 : 0.0);
    const double inv_width = (double)NW;         // 1/width, width = 1/NW

    double w[33];
    #pragma unroll
    for (int f = 0; f <= 32; f++) {
        double d = ((double)f / 32.0 - target) * inv_width;
        w[f] = exp(-d * d);
    }

    double acc = 0.0;
    for (int k = 0; k < 16; k++) {
        int dm = j - k + 64;                     // keep positive
        double c = w[0];
        #pragma unroll
        for (int f = 1; f <= 31; f++)
            c += 2.0 * w[f] * ctab[(dm * f) & 63];
        c += w[32] * ctab[(dm * 32) & 63];
        acc += (double)src[n * 16 + k] * c;
    }
    acc *= (1.0 / 64.0);

    vals[tid] = acc;
    __syncthreads();
    double ss = 0.0;
    const int base = tid & ~15;
    #pragma unroll
    for (int m = 0; m < 16; m++) { double v = vals[base + m]; ss += v * v; }
    double nrm = sqrt(ss);
    if (nrm < 1e-12) nrm = 1e-12;
    g_filt[bank][n][j] = (float)(acc / nrm * 1.4142135623730951);
}

// ---------------------------------------------------------------------------
// One DWT level: stride-2 cross-correlation with zero pad 15 each side.
// out[t] = sum_k f[k] * x[2t + k - 15]. Computes lp (approx) + hp (detail).
// One block = 256 outputs of one (batch, wavelet) row.
// ---------------------------------------------------------------------------
__global__ void __launch_bounds__(256)
dwt_level_kernel(const float* __restrict__ in, long in_stride, int in_len, int bcast,
                 float* __restrict__ approx, long approx_stride,
                 float* __restrict__ detail, long detail_stride, int out_len)
{
    __shared__ float s[526];                     // 2*255 + 15 + 1
    __shared__ float flp[16], fhp[16];

    const int r = blockIdx.y;                    // row = b*4 + n
    const int n = r & 3;
    if (threadIdx.x < 16) {
        flp[threadIdx.x] = g_filt[0][n][threadIdx.x];
        fhp[threadIdx.x] = g_filt[1][n][threadIdx.x];
    }

    const float* x = in + (bcast ? (long)(r >> 2) : (long)r) * in_stride;
    const int t0   = blockIdx.x * 256;
    const int base = 2 * t0 - 15;
    for (int i = threadIdx.x; i < 526; i += 256) {
        int gi = base + i;
        s[i] = (gi >= 0 && gi < in_len) ? x[gi] : 0.0f;
    }
    __syncthreads();

    const int t = t0 + threadIdx.x;
    if (t < out_len) {
        float a = 0.0f, d = 0.0f;
        const int si = 2 * threadIdx.x;
        #pragma unroll
        for (int k = 0; k < 16; k++) {
            float v = s[si + k];
            a = fmaf(flp[k], v, a);
            d = fmaf(fhp[k], v, d);
        }
        approx[(long)r * approx_stride + t] = a;
        detail[(long)r * detail_stride + t] = d;
    }
}

// ---------------------------------------------------------------------------
extern "C" void kernel_launch(void* const* d_in, const int* in_sizes, int n_in,
                              void* d_out, int out_size) {
    const float* signal = (const float*)d_in[0];
    const float* low    = (const float*)d_in[1];
    const float* high   = (const float*)d_in[2];
    float* out = (float*)d_out;

    float *bufA, *bufB;
    cudaGetSymbolAddress((void**)&bufA, g_bufA);
    cudaGetSymbolAddress((void**)&bufB, g_bufB);

    constrain_kernel<<<1, 128>>>(low, high);

    // Output row layout (per row of length T_OUT = 131166):
    //   [0,2063)        approx level 6
    //   [2063,4126)     detail level 6
    //   [4126,8237)     detail level 5
    //   [8237,16444)    detail level 4
    //   [16444,32842)   detail level 3
    //   [32842,65622)   detail level 2
    //   [65622,131166)  detail level 1
    auto launch = [&](const float* in, long istr, int ilen, int bc,
                      float* ap, long astr, float* de, int olen) {
        dim3 grid((unsigned)((olen + 255) / 256), ROWS);
        dwt_level_kernel<<<grid, 256>>>(in, istr, ilen, bc,
                                        ap, astr, de, (long)T_OUT, olen);
    };

    launch(signal, SIG_LEN, SIG_LEN, 1, bufA, 65544, out + 65622, 65544); // L1
    launch(bufA, 65544, 65544, 0,      bufB, 32780, out + 32842, 32780);  // L2
    launch(bufB, 32780, 32780, 0,      bufA, 16398, out + 16444, 16398);  // L3
    launch(bufA, 16398, 16398, 0,      bufB,  8207, out +  8237,  8207);  // L4
    launch(bufB,  8207,  8207, 0,      bufA,  4111, out +  4126,  4111);  // L5
    launch(bufA,  4111,  4111, 0,      out,  T_OUT, out +  2063,  2063);  // L6
}

// round 2
// speedup vs baseline: 1.0749x; 1.0749x over previous
#include <cuda_runtime.h>
#include <math.h>

// Problem constants
#define SIG_LEN   131072
#define BATCH     64
#define NW        4
#define ROWS      (BATCH * NW)        // 256
#define T_OUT     131166              // per-row output length
// Level output lengths: L[i] = (L[i-1] + 14)/2 + 1
// 131072 -> 65544 -> 32780 -> 16398 -> 8207 -> 4111 -> 2063

// Scratch ping-pong buffers (device globals: allocation-free per harness rules)
__device__ float g_bufA[(size_t)ROWS * 65544];   // levels 1,3,5 approx
__device__ float g_bufB[(size_t)ROWS * 32780];   // levels 2,4 approx
__device__ float g_filt[2][4][16];               // [lp/hp][wavelet][tap]

// ---------------------------------------------------------------------------
// Filter constraint: pad->rfft(64)->gaussian weight->irfft->trunc(16)->norm*sqrt2
// Linear map on the 16 taps; cos table has only 64 distinct values.
// ---------------------------------------------------------------------------
__global__ void constrain_kernel(const float* __restrict__ low,
                                 const float* __restrict__ high) {
    __shared__ double ctab[64];
    __shared__ double vals[128];
    const int tid = threadIdx.x;                 // 0..127
    if (tid < 64) ctab[tid] = cos(2.0 * M_PI * (double)tid / 64.0);
    __syncthreads();

    const int bank = tid >> 6;                   // 0 = lp, 1 = hp
    const int n    = (tid >> 4) & 3;             // wavelet
    const int j    = tid & 15;                   // output tap
    const float* src = bank ? high : low;

    const double target = ((double)n + 0.5) / (double)NW * 0.5 + (bank ? 0.5 : 0.0);
    const double inv_width = (double)NW;         // 1/width, width = 1/NW

    double w[33];
    #pragma unroll
    for (int f = 0; f <= 32; f++) {
        double d = ((double)f / 32.0 - target) * inv_width;
        w[f] = exp(-d * d);
    }

    double acc = 0.0;
    for (int k = 0; k < 16; k++) {
        int dm = j - k + 64;                     // keep positive
        double c = w[0];
        #pragma unroll
        for (int f = 1; f <= 31; f++)
            c += 2.0 * w[f] * ctab[(dm * f) & 63];
        c += w[32] * ctab[(dm * 32) & 63];
        acc += (double)src[n * 16 + k] * c;
    }
    acc *= (1.0 / 64.0);

    vals[tid] = acc;
    __syncthreads();
    double ss = 0.0;
    const int base = tid & ~15;
    #pragma unroll
    for (int m = 0; m < 16; m++) { double v = vals[base + m]; ss += v * v; }
    double nrm = sqrt(ss);
    if (nrm < 1e-12) nrm = 1e-12;
    g_filt[bank][n][j] = (float)(acc / nrm * 1.4142135623730951);
}

// ---------------------------------------------------------------------------
// Packed f32x2 FMA (sm_103a)
// ---------------------------------------------------------------------------
__device__ __forceinline__ unsigned long long fma2(unsigned long long a,
                                                   unsigned long long b,
                                                   unsigned long long c) {
    unsigned long long d;
    asm("fma.rn.f32x2 %0, %1, %2, %3;" : "=l"(d) : "l"(a), "l"(b), "l"(c));
    return d;
}
__device__ __forceinline__ float hsum2(unsigned long long a) {
    float2 v = *reinterpret_cast<float2*>(&a);
    return v.x + v.y;
}

// Skewed smem index: avoids bank conflicts for 32B-strided LDS.128
__device__ __forceinline__ int skew(int i) { return i + ((i >> 5) << 2); }

// ---------------------------------------------------------------------------
// One DWT level: out[t] = sum_k f[k] * x[2t + k - 15], stride-2, zero-padded.
// Each block: 1024 outputs of one (batch, wavelet) row; 4 outputs per thread.
// Window pairs P[p] = {s[2p], s[2p+1]} -> out[dt] = hsum( sum_m f2[m] (*) P[dt+m] ).
// ---------------------------------------------------------------------------
#define OPB 1024                       // outputs per block
#define SFILL 2064                     // window floats needed (2*1023 + 15 + pad)

__global__ void __launch_bounds__(256)
dwt_level_kernel(const float* __restrict__ in, long in_stride, int in_len, int bcast,
                 float* __restrict__ approx, long approx_stride,
                 float* __restrict__ detail, long detail_stride, int out_len)
{
    __shared__ float s[SFILL + 4 * (SFILL / 32) + 8];   // skewed layout

    const int tid = threadIdx.x;
    const int r = blockIdx.y;                    // row = b*4 + n
    const int n = r & 3;

    // Filters as packed float2 (uniform across block; L1 broadcast)
    const unsigned long long* fap = reinterpret_cast<const unsigned long long*>(g_filt[0][n]);
    const unsigned long long* fdp = reinterpret_cast<const unsigned long long*>(g_filt[1][n]);
    unsigned long long f2a[8], f2d[8];
    #pragma unroll
    for (int m = 0; m < 8; m++) { f2a[m] = __ldg(&fap[m]); f2d[m] = __ldg(&fdp[m]); }

    // Stage input window: s_lin[i] = x[2*t0 - 15 + i], zero-padded
    const float* x = in + (bcast ? (long)(r >> 2) : (long)r) * in_stride;
    const int t0   = blockIdx.x * OPB;
    const int base = 2 * t0 - 15;
    #pragma unroll 3
    for (int i = tid; i < SFILL; i += 256) {
        int gi = base + i;
        s[skew(i)] = (gi >= 0 && gi < in_len) ? x[gi] : 0.0f;
    }
    __syncthreads();

    // Load 12 window pairs (24 floats) via 6 aligned LDS.128
    unsigned long long P[12];
    #pragma unroll
    for (int k = 0; k < 6; k++) {
        int f = 8 * tid + 4 * k;                 // linear float index (mult of 4)
        const ulonglong2 q = *reinterpret_cast<const ulonglong2*>(&s[skew(f)]);
        P[2 * k]     = q.x;
        P[2 * k + 1] = q.y;
    }

    unsigned long long acc_a[4] = {0ull, 0ull, 0ull, 0ull};
    unsigned long long acc_d[4] = {0ull, 0ull, 0ull, 0ull};
    #pragma unroll
    for (int m = 0; m < 8; m++) {
        #pragma unroll
        for (int o = 0; o < 4; o++) {
            acc_a[o] = fma2(f2a[m], P[o + m], acc_a[o]);
            acc_d[o] = fma2(f2d[m], P[o + m], acc_d[o]);
        }
    }

    float* ap = approx + (long)r * approx_stride;
    float* dp = detail + (long)r * detail_stride;
    const int tb = t0 + 4 * tid;
    #pragma unroll
    for (int o = 0; o < 4; o++) {
        int t = tb + o;
        if (t < out_len) {
            ap[t] = hsum2(acc_a[o]);
            dp[t] = hsum2(acc_d[o]);
        }
    }
}

// ---------------------------------------------------------------------------
extern "C" void kernel_launch(void* const* d_in, const int* in_sizes, int n_in,
                              void* d_out, int out_size) {
    const float* signal = (const float*)d_in[0];
    const float* low    = (const float*)d_in[1];
    const float* high   = (const float*)d_in[2];
    float* out = (float*)d_out;

    float *bufA, *bufB;
    cudaGetSymbolAddress((void**)&bufA, g_bufA);
    cudaGetSymbolAddress((void**)&bufB, g_bufB);

    constrain_kernel<<<1, 128>>>(low, high);

    // Output row layout (per row of length T_OUT = 131166):
    //   [0,2063) approx L6 | [2063,4126) det L6 | [4126,8237) det L5
    //   [8237,16444) det L4 | [16444,32842) det L3 | [32842,65622) det L2
    //   [65622,131166) det L1
    auto launch = [&](const float* in, long istr, int ilen, int bc,
                      float* ap, long astr, float* de, int olen) {
        dim3 grid((unsigned)((olen + OPB - 1) / OPB), ROWS);
        dwt_level_kernel<<<grid, 256>>>(in, istr, ilen, bc,
                                        ap, astr, de, (long)T_OUT, olen);
    };

    launch(signal, SIG_LEN, SIG_LEN, 1, bufA, 65544, out + 65622, 65544); // L1
    launch(bufA, 65544, 65544, 0,      bufB, 32780, out + 32842, 32780);  // L2
    launch(bufB, 32780, 32780, 0,      bufA, 16398, out + 16444, 16398);  // L3
    launch(bufA, 16398, 16398, 0,      bufB,  8207, out +  8237,  8207);  // L4
    launch(bufB,  8207,  8207, 0,      bufA,  4111, out +  4126,  4111);  // L5
    launch(bufA,  4111,  4111, 0,      out,  T_OUT, out +  2063,  2063);  // L6
}

// round 3
// speedup vs baseline: 1.6359x; 1.5219x over previous
#include <cuda_runtime.h>
#include <math.h>

// Problem constants
#define SIG_LEN   131072
#define BATCH     64
#define NW        4
#define ROWS      (BATCH * NW)        // 256
#define T_OUT     131166              // per-row output length
#define SPLIT     8                   // blocks per row
#define CHK       (SIG_LEN / SPLIT)   // 16384 input samples owned per block
#define S         2048                // input samples per scan step

typedef unsigned long long ull;

__device__ float g_filt[2][4][16];    // [lp/hp][wavelet][tap]

// ---------------------------------------------------------------------------
// Filter constraint: pad->rfft(64)->gaussian weight->irfft->trunc(16)->norm*sqrt2
// ---------------------------------------------------------------------------
__global__ void constrain_kernel(const float* __restrict__ low,
                                 const float* __restrict__ high) {
    __shared__ double ctab[64];
    __shared__ double vals[128];
    const int tid = threadIdx.x;                 // 0..127
    if (tid < 64) ctab[tid] = cos(2.0 * M_PI * (double)tid / 64.0);
    __syncthreads();

    const int bank = tid >> 6;                   // 0 = lp, 1 = hp
    const int n    = (tid >> 4) & 3;             // wavelet
    const int j    = tid & 15;                   // output tap
    const float* src = bank ? high : low;

    const double target = ((double)n + 0.5) / (double)NW * 0.5 + (bank ? 0.5 : 0.0);
    const double inv_width = (double)NW;

    double w[33];
    #pragma unroll
    for (int f = 0; f <= 32; f++) {
        double d = ((double)f / 32.0 - target) * inv_width;
        w[f] = exp(-d * d);
    }

    double acc = 0.0;
    for (int k = 0; k < 16; k++) {
        int dm = j - k + 64;
        double c = w[0];
        #pragma unroll
        for (int f = 1; f <= 31; f++)
            c += 2.0 * w[f] * ctab[(dm * f) & 63];
        c += w[32] * ctab[(dm * 32) & 63];
        acc += (double)src[n * 16 + k] * c;
    }
    acc *= (1.0 / 64.0);

    vals[tid] = acc;
    __syncthreads();
    double ss = 0.0;
    const int base = tid & ~15;
    #pragma unroll
    for (int m = 0; m < 16; m++) { double v = vals[base + m]; ss += v * v; }
    double nrm = sqrt(ss);
    if (nrm < 1e-12) nrm = 1e-12;
    g_filt[bank][n][j] = (float)(acc / nrm * 1.4142135623730951);
}

// ---------------------------------------------------------------------------
__device__ __forceinline__ ull fma2(ull a, ull b, ull c) {
    ull d;
    asm("fma.rn.f32x2 %0, %1, %2, %3;" : "=l"(d) : "l"(a), "l"(b), "l"(c));
    return d;
}
__device__ __forceinline__ float hsum2(ull a) {
    float2 v = *reinterpret_cast<float2*>(&a);
    return v.x + v.y;
}

// ---------------------------------------------------------------------------
// Fully fused 6-level DWT. Grid (SPLIT, ROWS), 256 threads.
// Each block scans its input chunk (+2048 halo) in steps of S=2048 samples,
// cascading all 6 levels in smem with 15-sample carry tails per level.
// Buffer layout per level: [0..14] carry = prev 15 samples, [15..15+n) new.
// out_l[t] window = buf[2u .. 2u+15], u = t - tbase. Only details (+ final
// approx) ever touch gmem; each output element written exactly once chip-wide.
// ---------------------------------------------------------------------------
__global__ void __launch_bounds__(256, 3)
fused_dwt_kernel(const float* __restrict__ signal, float* __restrict__ out)
{
    __shared__ __align__(16) float s_in[15 + S    + 5];
    __shared__ __align__(16) float s_l1[15 + 1024 + 5];
    __shared__ __align__(16) float s_l2[15 + 512  + 5];
    __shared__ __align__(16) float s_l3[15 + 256  + 5];
    __shared__ __align__(16) float s_l4[15 + 128  + 5];
    __shared__ __align__(16) float s_l5[15 + 64   + 5];

    const int tid = threadIdx.x;
    const int j   = blockIdx.x;                  // chunk within row
    const int r   = blockIdx.y;                  // row = b*4 + n
    const int n   = r & 3;
    const float* x = signal + (size_t)(r >> 2) * SIG_LEN;
    float* orow = out + (size_t)r * T_OUT;

    // Filters as packed f32x2 in registers
    ull fa[8], fd[8];
    {
        const ull* fap = (const ull*)g_filt[0][n];
        const ull* fdp = (const ull*)g_filt[1][n];
        #pragma unroll
        for (int m = 0; m < 8; m++) { fa[m] = __ldg(fap + m); fd[m] = __ldg(fdp + m); }
    }

    // Zero carries (left zero-pad semantics / halo transient flush)
    if (tid < 15) {
        s_in[tid] = 0.f; s_l1[tid] = 0.f; s_l2[tid] = 0.f;
        s_l3[tid] = 0.f; s_l4[tid] = 0.f; s_l5[tid] = 0.f;
    }

    // Level output lengths and detail segment offsets within an out row
    const int   Lout[6] = {65544, 32780, 16398, 8207, 4111, 2063};
    float* gd1 = orow + 65622;  float* gd2 = orow + 32842;
    float* gd3 = orow + 16444;  float* gd4 = orow + 8237;
    float* gd5 = orow + 4126;   float* gd6 = orow + 2063;

    int olo[6], ohi[6];
    #pragma unroll
    for (int l = 0; l < 6; l++) {
        int c = CHK >> (l + 1);
        olo[l] = j * c;
        ohi[l] = (j == SPLIT - 1) ? Lout[l] : (j + 1) * c;
    }

    // One level: n_out outputs from src into dst (+ masked gmem writes).
    auto level = [&](const float* __restrict__ src, float* __restrict__ dst,
                     int n_out, int tbase, float* __restrict__ det,
                     int lo, int hi, float* __restrict__ app)
    {
        for (int u0 = 2 * tid; u0 < n_out; u0 += 512) {
            const float* w = src + 2 * u0;       // 16B aligned (u0 even)
            ulonglong2 v0 = *(const ulonglong2*)(w);
            ulonglong2 v1 = *(const ulonglong2*)(w + 4);
            ulonglong2 v2 = *(const ulonglong2*)(w + 8);
            ulonglong2 v3 = *(const ulonglong2*)(w + 12);
            ull p8 = *(const ull*)(w + 16);
            ull P[9] = {v0.x, v0.y, v1.x, v1.y, v2.x, v2.y, v3.x, v3.y, p8};
            ull a0 = 0ull, a1 = 0ull, d0 = 0ull, d1 = 0ull;
            #pragma unroll
            for (int m = 0; m < 8; m++) {
                a0 = fma2(fa[m], P[m],     a0);
                d0 = fma2(fd[m], P[m],     d0);
                a1 = fma2(fa[m], P[m + 1], a1);
                d1 = fma2(fd[m], P[m + 1], d1);
            }
            float ra0 = hsum2(a0), ra1 = hsum2(a1);
            float rd0 = hsum2(d0), rd1 = hsum2(d1);
            if (dst) { dst[15 + u0] = ra0; dst[16 + u0] = ra1; }
            int t0 = tbase + u0;
            if (t0 >= lo && t0 < hi)         { det[t0]     = rd0; if (app) app[t0]     = ra0; }
            if (t0 + 1 >= lo && t0 + 1 < hi) { det[t0 + 1] = rd1; if (app) app[t0 + 1] = ra1; }
        }
    };

    const int P0 = j * CHK - S;                  // scan start (includes halo)
    const int nstep = (j == SPLIT - 1) ? 10 : 9; // last block covers padded tail

    for (int step = 0; step < nstep; step++) {
        const int pin = P0 + step * S;
        __syncthreads();                         // carries ready / prev reads done

        // Stage S new input samples (zero-extended outside [0, SIG_LEN))
        if (pin >= 0 && pin + S <= SIG_LEN) {
            const float4* xp = (const float4*)(x + pin);
            #pragma unroll
            for (int c = 0; c < 2; c++) {
                float4 v = xp[tid + 256 * c];
                int i = 15 + 4 * (tid + 256 * c);
                s_in[i] = v.x; s_in[i+1] = v.y; s_in[i+2] = v.z; s_in[i+3] = v.w;
            }
        } else {
            for (int i = tid; i < S; i += 256) {
                int gi = pin + i;
                s_in[15 + i] = (gi >= 0 && gi < SIG_LEN) ? __ldg(x + gi) : 0.f;
            }
        }
        __syncthreads();

        level(s_in, s_l1, 1024, pin >> 1, gd1, olo[0], ohi[0], (float*)0);
        __syncthreads();
        level(s_l1, s_l2,  512, pin >> 2, gd2, olo[1], ohi[1], (float*)0);
        __syncthreads();
        level(s_l2, s_l3,  256, pin >> 3, gd3, olo[2], ohi[2], (float*)0);
        __syncthreads();
        level(s_l3, s_l4,  128, pin >> 4, gd4, olo[3], ohi[3], (float*)0);
        __syncthreads();
        level(s_l4, s_l5,   64, pin >> 5, gd5, olo[4], ohi[4], (float*)0);
        __syncthreads();
        level(s_l5, (float*)0, 32, pin >> 6, gd6, olo[5], ohi[5], orow);
        __syncthreads();

        // Carry tails: buf[0..14] = last 15 new samples
        if      (tid < 15)              s_in[tid]      = s_in[S    + tid];
        else if (tid >= 16 && tid < 31) s_l1[tid - 16] = s_l1[1024 + tid - 16];
        else if (tid >= 32 && tid < 47) s_l2[tid - 32] = s_l2[512  + tid - 32];
        else if (tid >= 48 && tid < 63) s_l3[tid - 48] = s_l3[256  + tid - 48];
        else if (tid >= 64 && tid < 79) s_l4[tid - 64] = s_l4[128  + tid - 64];
        else if (tid >= 80 && tid < 95) s_l5[tid - 80] = s_l5[64   + tid - 80];
    }
}

// ---------------------------------------------------------------------------
extern "C" void kernel_launch(void* const* d_in, const int* in_sizes, int n_in,
                              void* d_out, int out_size) {
    const float* signal = (const float*)d_in[0];
    const float* low    = (const float*)d_in[1];
    const float* high   = (const float*)d_in[2];
    float* out = (float*)d_out;

    constrain_kernel<<<1, 128>>>(low, high);

    dim3 grid(SPLIT, ROWS);
    fused_dwt_kernel<<<grid, 256>>>(signal, out);
}

// round 4
// speedup vs baseline: 2.0359x; 1.2445x over previous
#include <cuda_runtime.h>
#include <math.h>

// Problem constants
#define SIG_LEN   131072
#define BATCH     64
#define NW        4
#define ROWS      (BATCH * NW)        // 256
#define T_OUT     131166              // per-row output length
#define SPLIT     8                   // blocks per row
#define CHK       (SIG_LEN / SPLIT)   // 16384 input samples owned per block
#define S         2048                // input samples per scan step

// Skewed smem index: conflict-free for 32B-strided LDS.128 and 16B-strided STS
#define MP(i) ((i) + ((((i) >> 5)) << 2))

typedef unsigned long long ull;

__device__ float g_filt[2][4][16];    // [lp/hp][wavelet][tap]

// ---------------------------------------------------------------------------
// Filter constraint (fp32): pad->rfft(64)->gauss weight->irfft->trunc->norm*sqrt2
// ---------------------------------------------------------------------------
__global__ void constrain_kernel(const float* __restrict__ low,
                                 const float* __restrict__ high) {
    __shared__ float ctab[64];
    __shared__ float vals[128];
    const int tid = threadIdx.x;                 // 0..127
    if (tid < 64) ctab[tid] = cosf(2.0f * (float)M_PI * (float)tid / 64.0f);
    __syncthreads();

    const int bank = tid >> 6;                   // 0 = lp, 1 = hp
    const int n    = (tid >> 4) & 3;             // wavelet
    const int j    = tid & 15;                   // output tap
    const float* src = bank ? high : low;

    const float target = ((float)n + 0.5f) / (float)NW * 0.5f + (bank ? 0.5f : 0.0f);
    const float inv_width = (float)NW;

    float w[33];
    #pragma unroll
    for (int f = 0; f <= 32; f++) {
        float d = ((float)f / 32.0f - target) * inv_width;
        w[f] = expf(-d * d);
    }

    float acc = 0.0f;
    for (int k = 0; k < 16; k++) {
        int dm = j - k + 64;
        float c = w[0];
        #pragma unroll
        for (int f = 1; f <= 31; f++)
            c = fmaf(2.0f * w[f], ctab[(dm * f) & 63], c);
        c = fmaf(w[32], ctab[(dm * 32) & 63], c);
        acc = fmaf(src[n * 16 + k], c, acc);
    }
    acc *= (1.0f / 64.0f);

    vals[tid] = acc;
    __syncthreads();
    float ss = 0.0f;
    const int base = tid & ~15;
    #pragma unroll
    for (int m = 0; m < 16; m++) { float v = vals[base + m]; ss = fmaf(v, v, ss); }
    float nrm = sqrtf(ss);
    if (nrm < 1e-12f) nrm = 1e-12f;
    g_filt[bank][n][j] = acc / nrm * 1.41421356237309515f;
}

// ---------------------------------------------------------------------------
__device__ __forceinline__ ull fma2(ull a, ull b, ull c) {
    ull d;
    asm("fma.rn.f32x2 %0, %1, %2, %3;" : "=l"(d) : "l"(a), "l"(b), "l"(c));
    return d;
}
__device__ __forceinline__ float hsum2(ull a) {
    float2 v = *reinterpret_cast<float2*>(&a);
    return v.x + v.y;
}

// ---------------------------------------------------------------------------
// Fully fused 6-level DWT. Grid (SPLIT, ROWS), 256 threads.
// Each block scans its chunk (+2048 halo) in S=2048 steps, cascading 6 levels
// in skewed smem with 15-sample carries. 4 outputs per thread per level pass.
// ---------------------------------------------------------------------------
__global__ void __launch_bounds__(256, 3)
fused_dwt_kernel(const float* __restrict__ signal, float* __restrict__ out)
{
    __shared__ __align__(16) float s_in[2336];   // MP(15 + 2048 + pad)
    __shared__ __align__(16) float s_l1[1184];
    __shared__ __align__(16) float s_l2[608];
    __shared__ __align__(16) float s_l3[320];
    __shared__ __align__(16) float s_l4[176];
    __shared__ __align__(16) float s_l5[104];

    const int tid = threadIdx.x;
    const int j   = blockIdx.x;                  // chunk within row
    const int r   = blockIdx.y;                  // row = b*4 + n
    const int n   = r & 3;
    const float* x = signal + (size_t)(r >> 2) * SIG_LEN;
    float* orow = out + (size_t)r * T_OUT;

    // Filters as packed f32x2 in registers
    ull fa[8], fd[8];
    {
        const ull* fap = (const ull*)g_filt[0][n];
        const ull* fdp = (const ull*)g_filt[1][n];
        #pragma unroll
        for (int m = 0; m < 8; m++) { fa[m] = __ldg(fap + m); fd[m] = __ldg(fdp + m); }
    }

    // Zero carries (MP(i) == i for i < 15)
    if (tid < 15) {
        s_in[tid] = 0.f; s_l1[tid] = 0.f; s_l2[tid] = 0.f;
        s_l3[tid] = 0.f; s_l4[tid] = 0.f; s_l5[tid] = 0.f;
    }

    const int   Lout[6] = {65544, 32780, 16398, 8207, 4111, 2063};
    float* gd1 = orow + 65622;  float* gd2 = orow + 32842;
    float* gd3 = orow + 16444;  float* gd4 = orow + 8237;
    float* gd5 = orow + 4126;   float* gd6 = orow + 2063;

    int olo[6], ohi[6];
    #pragma unroll
    for (int l = 0; l < 6; l++) {
        int c = CHK >> (l + 1);
        olo[l] = j * c;
        ohi[l] = (j == SPLIT - 1) ? Lout[l] : (j + 1) * c;
    }

    // One level: n_out outputs from skewed src into skewed dst (+ masked gmem).
    // Output u window = src floats [2u, 2u+15]; 4 outputs/thread.
    auto level = [&](const float* __restrict__ src, float* __restrict__ dst,
                     int n_out, int tbase, float* __restrict__ det,
                     int lo, int hi, float* __restrict__ app)
    {
        for (int u0 = 4 * tid; u0 < n_out; u0 += 1024) {
            const int b0 = 2 * u0;               // multiple of 8
            ulonglong2 v0 = *(const ulonglong2*)(src + MP(b0));
            ulonglong2 v1 = *(const ulonglong2*)(src + MP(b0 + 4));
            ulonglong2 v2 = *(const ulonglong2*)(src + MP(b0 + 8));
            ulonglong2 v3 = *(const ulonglong2*)(src + MP(b0 + 12));
            ulonglong2 v4 = *(const ulonglong2*)(src + MP(b0 + 16));
            ulonglong2 v5 = *(const ulonglong2*)(src + MP(b0 + 20));
            ull P[12] = {v0.x, v0.y, v1.x, v1.y, v2.x, v2.y,
                         v3.x, v3.y, v4.x, v4.y, v5.x, v5.y};
            ull aa[4] = {0ull, 0ull, 0ull, 0ull};
            ull dd[4] = {0ull, 0ull, 0ull, 0ull};
            #pragma unroll
            for (int m = 0; m < 8; m++) {
                #pragma unroll
                for (int o = 0; o < 4; o++) {
                    aa[o] = fma2(fa[m], P[o + m], aa[o]);
                    dd[o] = fma2(fd[m], P[o + m], dd[o]);
                }
            }
            float ra[4], rd[4];
            #pragma unroll
            for (int o = 0; o < 4; o++) { ra[o] = hsum2(aa[o]); rd[o] = hsum2(dd[o]); }
            if (dst) {
                #pragma unroll
                for (int o = 0; o < 4; o++) dst[MP(15 + u0 + o)] = ra[o];
            }
            const int t0 = tbase + u0;
            #pragma unroll
            for (int o = 0; o < 4; o++) {
                int t = t0 + o;
                if (t >= lo && t < hi) { det[t] = rd[o]; if (app) app[t] = ra[o]; }
            }
        }
    };

    const int P0 = j * CHK - S;                  // scan start (includes halo)
    const int nstep = (j == SPLIT - 1) ? 10 : 9; // last block covers padded tail

    for (int step = 0; step < nstep; step++) {
        const int pin = P0 + step * S;
        __syncthreads();                         // carries ready / prev reads done

        // Stage S new input samples (zero-extended outside [0, SIG_LEN))
        if (pin >= 0 && pin + S <= SIG_LEN) {
            const float4* xp = (const float4*)(x + pin);
            #pragma unroll
            for (int c = 0; c < 2; c++) {
                float4 v = xp[tid + 256 * c];
                int i = 15 + 4 * (tid + 256 * c);
                s_in[MP(i)]     = v.x; s_in[MP(i + 1)] = v.y;
                s_in[MP(i + 2)] = v.z; s_in[MP(i + 3)] = v.w;
            }
        } else {
            for (int i = tid; i < S; i += 256) {
                int gi = pin + i;
                s_in[MP(15 + i)] = (gi >= 0 && gi < SIG_LEN) ? __ldg(x + gi) : 0.f;
            }
        }
        __syncthreads();

        level(s_in, s_l1, 1024, pin >> 1, gd1, olo[0], ohi[0], (float*)0);
        __syncthreads();
        level(s_l1, s_l2,  512, pin >> 2, gd2, olo[1], ohi[1], (float*)0);
        __syncthreads();
        level(s_l2, s_l3,  256, pin >> 3, gd3, olo[2], ohi[2], (float*)0);
        __syncthreads();
        level(s_l3, s_l4,  128, pin >> 4, gd4, olo[3], ohi[3], (float*)0);
        __syncthreads();
        level(s_l4, s_l5,   64, pin >> 5, gd5, olo[4], ohi[4], (float*)0);
        __syncthreads();
        level(s_l5, (float*)0, 32, pin >> 6, gd6, olo[5], ohi[5], orow);
        __syncthreads();

        // Carry tails: buf[0..14] = last 15 new samples
        if      (tid < 15)              s_in[tid]      = s_in[MP(S    + tid)];
        else if (tid >= 16 && tid < 31) s_l1[tid - 16] = s_l1[MP(1024 + tid - 16)];
        else if (tid >= 32 && tid < 47) s_l2[tid - 32] = s_l2[MP(512  + tid - 32)];
        else if (tid >= 48 && tid < 63) s_l3[tid - 48] = s_l3[MP(256  + tid - 48)];
        else if (tid >= 64 && tid < 79) s_l4[tid - 64] = s_l4[MP(128  + tid - 64)];
        else if (tid >= 80 && tid < 95) s_l5[tid - 80] = s_l5[MP(64   + tid - 80)];
    }
}

// ---------------------------------------------------------------------------
extern "C" void kernel_launch(void* const* d_in, const int* in_sizes, int n_in,
                              void* d_out, int out_size) {
    const float* signal = (const float*)d_in[0];
    const float* low    = (const float*)d_in[1];
    const float* high   = (const float*)d_in[2];
    float* out = (float*)d_out;

    constrain_kernel<<<1, 128>>>(low, high);

    dim3 grid(SPLIT, ROWS);
    fused_dwt_kernel<<<grid, 256>>>(signal, out);
}

// round 5
// speedup vs baseline: 2.6698x; 1.3113x over previous
#include <cuda_runtime.h>
#include <math.h>

// Problem constants
#define SIG_LEN   131072
#define NW        4
#define ROWS      256
#define T_OUT     131166
#define SPLIT     8
#define CHK       16384               // input samples owned per block
#define SS        2048                // input samples per scan step

typedef unsigned long long ull;

__device__ float g_filt[2][4][16];    // [lp/hp][wavelet][tap]

// ---------------------------------------------------------------------------
// Filter constraint (fp32): pad->rfft(64)->gauss weight->irfft->trunc->norm*sqrt2
// ---------------------------------------------------------------------------
__global__ void constrain_kernel(const float* __restrict__ low,
                                 const float* __restrict__ high) {
    __shared__ float ctab[64];
    __shared__ float vals[128];
    const int tid = threadIdx.x;                 // 0..127
    if (tid < 64) ctab[tid] = cosf(2.0f * (float)M_PI * (float)tid / 64.0f);
    __syncthreads();

    const int bank = tid >> 6;                   // 0 = lp, 1 = hp
    const int n    = (tid >> 4) & 3;             // wavelet
    const int j    = tid & 15;                   // output tap
    const float* src = bank ? high : low;

    const float target = ((float)n + 0.5f) / (float)NW * 0.5f + (bank ? 0.5f : 0.0f);
    const float inv_width = (float)NW;

    float w[33];
    #pragma unroll
    for (int f = 0; f <= 32; f++) {
        float d = ((float)f / 32.0f - target) * inv_width;
        w[f] = expf(-d * d);
    }

    float acc = 0.0f;
    for (int k = 0; k < 16; k++) {
        int dm = j - k + 64;
        float c = w[0];
        #pragma unroll
        for (int f = 1; f <= 31; f++)
            c = fmaf(2.0f * w[f], ctab[(dm * f) & 63], c);
        c = fmaf(w[32], ctab[(dm * 32) & 63], c);
        acc = fmaf(src[n * 16 + k], c, acc);
    }
    acc *= (1.0f / 64.0f);

    vals[tid] = acc;
    __syncthreads();
    float ss = 0.0f;
    const int base = tid & ~15;
    #pragma unroll
    for (int m = 0; m < 16; m++) { float v = vals[base + m]; ss = fmaf(v, v, ss); }
    float nrm = sqrtf(ss);
    if (nrm < 1e-12f) nrm = 1e-12f;
    g_filt[bank][n][j] = acc / nrm * 1.41421356237309515f;
}

// ---------------------------------------------------------------------------
__device__ __forceinline__ ull fma2(ull a, ull b, ull c) {
    ull d;
    asm("fma.rn.f32x2 %0, %1, %2, %3;" : "=l"(d) : "l"(a), "l"(b), "l"(c));
    return d;
}
__device__ __forceinline__ float hsum2(ull a) {
    float2 v = *reinterpret_cast<float2*>(&a);
    return v.x + v.y;
}

// Shared-memory arena layout (floats). Step phase: s_in, s_l1. Tail phase
// reuses the same space for s_l3, s_l4, s_l5. s_a2 persists across both.
#define OFF_IN  0      // 2080 floats (window of 2063)
#define OFF_L1  2080   // 1056 floats (15 carry + 1024)
#define OFF_L3  0      // 2208 floats
#define OFF_L4  2208   // 1120 floats
#define OFF_L5  3328   // 576 floats
#define OFF_A2  3904   // 4656 floats (l2 approx, whole chunk + halo, +3 shift)
#define ARENA   8560

// ---------------------------------------------------------------------------
// Fused 6-level DWT. Grid (SPLIT, ROWS), 256 threads.
// Step loop: stage input, level1, level2 (l2 approx -> persistent s_a2).
// Tail: levels 3..6 once over the whole chunk (+ left halo cone 112/48/16).
// Conv: out[t] = sum_k f[k] x[2t+k-15]  (window x[2t-15 .. 2t], backward).
// Buffers store child values so that output q's window = buf[woff+2q .. +15],
// with woff and per-thread bases multiples of 4 (16B-aligned LDS.128).
// ---------------------------------------------------------------------------
__global__ void __launch_bounds__(256, 3)
fused_dwt_kernel(const float* __restrict__ signal, float* __restrict__ out)
{
    __shared__ __align__(16) float sm[ARENA];
    const int tid = threadIdx.x;
    const int j   = blockIdx.x;                  // chunk within row
    const int r   = blockIdx.y;                  // row = b*4 + n
    const int n   = r & 3;
    const float* x = signal + (size_t)(r >> 2) * SIG_LEN;
    float* orow = out + (size_t)r * T_OUT;

    // Filters as packed f32x2 in registers
    ull fa[8], fd[8];
    {
        const ull* fap = (const ull*)g_filt[0][n];
        const ull* fdp = (const ull*)g_filt[1][n];
        #pragma unroll
        for (int m = 0; m < 8; m++) { fa[m] = __ldg(fap + m); fd[m] = __ldg(fdp + m); }
    }

    // Init zeros: s_l1 tail (first carry source), s_a2 head pad + tail zeros
    if (tid < 15)                 sm[OFF_L1 + 1024 + tid] = 0.f;
    if (tid >= 32 && tid < 35)    sm[OFF_A2 + (tid - 32)] = 0.f;
    if (tid >= 64 && tid < 112)   sm[OFF_A2 + 4608 + (tid - 64)] = 0.f;

    const int Lout[6] = {65544, 32780, 16398, 8207, 4111, 2063};
    int olo[6], ohi[6];
    #pragma unroll
    for (int l = 0; l < 6; l++) {
        int c = CHK >> (l + 1);
        olo[l] = j * c;
        ohi[l] = (j == SPLIT - 1) ? Lout[l] : (j + 1) * c;
    }
    float* gd1 = orow + 65622;  float* gd2 = orow + 32842;
    float* gd3 = orow + 16444;  float* gd4 = orow + 8237;
    float* gd5 = orow + 4126;   float* gd6 = orow + 2063;

    // Generic level pass: outputs q in [0, nq) (2 per thread per iter),
    // global index t = tg0 + q. Window = src[woff+2q .. woff+2q+15].
    auto level = [&](const float* __restrict__ src, int woff,
                     float* __restrict__ dst, int dst0, int dqlim,
                     float* __restrict__ det, int tg0, int lo, int hi,
                     float* __restrict__ app, int nq)
    {
        for (int q = 2 * tid; q < nq; q += 512) {
            const float* w = src + woff + 2 * q;
            ulonglong2 v0 = *(const ulonglong2*)(w);
            ulonglong2 v1 = *(const ulonglong2*)(w + 4);
            ulonglong2 v2 = *(const ulonglong2*)(w + 8);
            ulonglong2 v3 = *(const ulonglong2*)(w + 12);
            ull p8 = *(const ull*)(w + 16);
            ull P[9] = {v0.x, v0.y, v1.x, v1.y, v2.x, v2.y, v3.x, v3.y, p8};
            ull a0 = 0ull, a1 = 0ull, d0 = 0ull, d1 = 0ull;
            #pragma unroll
            for (int m = 0; m < 8; m++) {
                a0 = fma2(fa[m], P[m],     a0);
                d0 = fma2(fd[m], P[m],     d0);
                a1 = fma2(fa[m], P[m + 1], a1);
                d1 = fma2(fd[m], P[m + 1], d1);
            }
            float ra0 = hsum2(a0), ra1 = hsum2(a1);
            float rd0 = hsum2(d0), rd1 = hsum2(d1);
            if (dst) {
                if (q < dqlim)     dst[dst0 + q]     = ra0;
                if (q + 1 < dqlim) dst[dst0 + q + 1] = ra1;
            }
            const int t = tg0 + q;
            if (t >= lo && t < hi)         { det[t]     = rd0; if (app) app[t]     = ra0; }
            if (t+1 >= lo && t+1 < hi)     { det[t + 1] = rd1; if (app) app[t + 1] = ra1; }
        }
    };

    const int base2 = j * 4096 - 512;            // first l2 index covered
    const int P0    = j * CHK - SS;              // scan start (left halo)
    const int nstep = (j == SPLIT - 1) ? 10 : 9;

    for (int step = 0; step < nstep; step++) {
        const int pin = P0 + step * SS;
        __syncthreads();                         // prev L1/L2 reads done

        // s_l1 carry (head <- tail) + stage s_in[i] = x[pin-15+i], i in [0,2063)
        if (tid < 15) sm[OFF_L1 + tid] = sm[OFF_L1 + 1024 + tid];
        #pragma unroll
        for (int c = 0; c < 8; c++) {
            int i = tid + 256 * c;
            int gi = pin - 15 + i;
            sm[OFF_IN + i] = (gi >= 0 && gi < SIG_LEN) ? __ldg(x + gi) : 0.f;
        }
        if (tid < 15) {
            int i = tid + 2048;
            int gi = pin - 15 + i;
            sm[OFF_IN + i] = (gi >= 0 && gi < SIG_LEN) ? __ldg(x + gi) : 0.f;
        }
        __syncthreads();

        // Level 1: 1024 outputs at u = (pin>>1)+q; approx -> s_l1[15+q]
        level(sm + OFF_IN, 0, sm + OFF_L1, 15, 1 << 30,
              gd1, pin >> 1, olo[0], ohi[0], (float*)0, 1024);
        __syncthreads();

        // Level 2: 512 outputs at u2 = (pin>>2)+q; approx -> s_a2[step*512+3+q]
        level(sm + OFF_L1, 0, sm + OFF_A2, step * 512 + 3,
              Lout[1] - (base2 + step * 512),
              gd2, pin >> 2, olo[1], ohi[1], (float*)0, 512);
    }

    __syncthreads();
    // Zero tail-buffer pads (heads [0,3) and right-edge zero regions)
    if (tid < 3) { sm[OFF_L3 + tid] = 0.f; sm[OFF_L4 + tid] = 0.f; sm[OFF_L5 + tid] = 0.f; }
    if (tid >= 32 && tid < 63)  sm[OFF_L3 + 2177 + (tid - 32)] = 0.f;
    if (tid >= 64 && tid < 94)  sm[OFF_L4 + 1090 + (tid - 64)] = 0.f;
    if (tid >= 96 && tid < 126) sm[OFF_L5 +  546 + (tid - 96)] = 0.f;
    __syncthreads();

    // Tail: levels 3..6 once. Left halos 112/48/16 cover the dependency cone.
    {
        const int a3 = olo[2] - 112, n3 = ohi[2] - a3;      // even
        level(sm + OFF_A2, 276, sm + OFF_L3, 3, 1 << 30,
              gd3, a3, olo[2], ohi[2], (float*)0, n3);
        __syncthreads();

        const int a4 = olo[3] - 48, n4 = ohi[3] - a4;
        level(sm + OFF_L3, 4, sm + OFF_L4, 3, 1 << 30,
              gd4, a4, olo[3], ohi[3], (float*)0, n4);
        __syncthreads();

        const int a5 = olo[4] - 16, n5 = ohi[4] - a5;
        level(sm + OFF_L4, 4, sm + OFF_L5, 3, 1 << 30,
              gd5, a5, olo[4], ohi[4], (float*)0, n5);
        __syncthreads();

        level(sm + OFF_L5, 4, (float*)0, 0, 0,
              gd6, olo[5], olo[5], ohi[5], orow, ohi[5] - olo[5]);
    }
}

// ---------------------------------------------------------------------------
extern "C" void kernel_launch(void* const* d_in, const int* in_sizes, int n_in,
                              void* d_out, int out_size) {
    const float* signal = (const float*)d_in[0];
    const float* low    = (const float*)d_in[1];
    const float* high   = (const float*)d_in[2];
    float* out = (float*)d_out;

    constrain_kernel<<<1, 128>>>(low, high);

    dim3 grid(SPLIT, ROWS);
    fused_dwt_kernel<<<grid, 256>>>(signal, out);
}

// round 7
// speedup vs baseline: 2.8854x; 1.0808x over previous
#include <cuda_runtime.h>
#include <math.h>
#include <stdint.h>

// Problem constants
#define SIG_LEN   131072
#define NW        4
#define ROWS      256
#define T_OUT     131166
#define SPLIT     8
#define CHK       16384               // input samples owned per block
#define SS        2048                // input samples per scan step

typedef unsigned long long ull;

__device__ float g_filt[2][4][16];    // [lp/hp][wavelet][tap]

// ---------------------------------------------------------------------------
// Filter constraint (fp32): pad->rfft(64)->gauss weight->irfft->trunc->norm*sqrt2
// ---------------------------------------------------------------------------
__global__ void constrain_kernel(const float* __restrict__ low,
                                 const float* __restrict__ high) {
    __shared__ float ctab[64];
    __shared__ float vals[128];
    const int tid = threadIdx.x;                 // 0..127
    if (tid < 64) ctab[tid] = cosf(2.0f * (float)M_PI * (float)tid / 64.0f);
    __syncthreads();

    const int bank = tid >> 6;                   // 0 = lp, 1 = hp
    const int n    = (tid >> 4) & 3;             // wavelet
    const int j    = tid & 15;                   // output tap
    const float* src = bank ? high : low;

    const float target = ((float)n + 0.5f) / (float)NW * 0.5f + (bank ? 0.5f : 0.0f);
    const float inv_width = (float)NW;

    float w[33];
    #pragma unroll
    for (int f = 0; f <= 32; f++) {
        float d = ((float)f / 32.0f - target) * inv_width;
        w[f] = expf(-d * d);
    }

    float acc = 0.0f;
    for (int k = 0; k < 16; k++) {
        int dm = j - k + 64;
        float c = w[0];
        #pragma unroll
        for (int f = 1; f <= 31; f++)
            c = fmaf(2.0f * w[f], ctab[(dm * f) & 63], c);
        c = fmaf(w[32], ctab[(dm * 32) & 63], c);
        acc = fmaf(src[n * 16 + k], c, acc);
    }
    acc *= (1.0f / 64.0f);

    vals[tid] = acc;
    __syncthreads();
    float ss = 0.0f;
    const int base = tid & ~15;
    #pragma unroll
    for (int m = 0; m < 16; m++) { float v = vals[base + m]; ss = fmaf(v, v, ss); }
    float nrm = sqrtf(ss);
    if (nrm < 1e-12f) nrm = 1e-12f;
    g_filt[bank][n][j] = acc / nrm * 1.41421356237309515f;
}

// ---------------------------------------------------------------------------
__device__ __forceinline__ ull fma2(ull a, ull b, ull c) {
    ull d;
    asm("fma.rn.f32x2 %0, %1, %2, %3;" : "=l"(d) : "l"(a), "l"(b), "l"(c));
    return d;
}
__device__ __forceinline__ float hsum2(ull a) {
    float2 v = *reinterpret_cast<float2*>(&a);
    return v.x + v.y;
}

// Shared-memory arena (floats). Step phase: s_in0, s_in1, s_l1, s_a2.
// Tail phase overlays s_l3/l4/l5 on the s_in region. s_a2 persists.
#define OFF_IN0 0      // 2080 floats
#define OFF_IN1 2080   // 2080 floats
#define OFF_L1  4160   // 1056 floats (15 carry + 1024)
#define OFF_L3  0      // 2208 floats (tail overlay)
#define OFF_L4  2208   // 1120 floats
#define OFF_L5  3328   // 576 floats
#define OFF_A2  5216   // 4656 floats (l2 approx: chunk + halo, +3 shift)
#define ARENA   9872

// ---------------------------------------------------------------------------
// Fused 6-level DWT. Grid (SPLIT, ROWS), 256 threads.
// Step loop (double-buffered cp.async staging): stage s+1, level1, level2.
// Tail: levels 3..6 once over the chunk (+ left halo cone 112/48/16).
// Conv: out[t] = sum_k f[k] x[2t+k-15]; window q -> src[woff+2q .. +17],
// per-thread bases multiples of 4 floats (16B-aligned LDS.128).
// ---------------------------------------------------------------------------
__global__ void __launch_bounds__(256, 3)
fused_dwt_kernel(const float* __restrict__ signal, float* __restrict__ out)
{
    __shared__ __align__(16) float sm[ARENA];
    const int tid = threadIdx.x;
    const int j   = blockIdx.x;                  // chunk within row
    const int r   = blockIdx.y;                  // row = b*4 + n
    const int n   = r & 3;
    const float* x = signal + (size_t)(r >> 2) * SIG_LEN;
    float* orow = out + (size_t)r * T_OUT;

    uint32_t smb;
    asm("{ .reg .u64 t; cvta.to.shared.u64 t, %1; cvt.u32.u64 %0, t; }"
        : "=r"(smb) : "l"(sm));

    // Filters as packed f32x2 in registers
    ull fa[8], fd[8];
    {
        const ull* fap = (const ull*)g_filt[0][n];
        const ull* fdp = (const ull*)g_filt[1][n];
        #pragma unroll
        for (int m = 0; m < 8; m++) { fa[m] = __ldg(fap + m); fd[m] = __ldg(fdp + m); }
    }

    // Init zeros: s_l1 tail (first carry source), s_a2 head pad + tail zeros
    if (tid < 15)                 sm[OFF_L1 + 1024 + tid] = 0.f;
    if (tid >= 32 && tid < 35)    sm[OFF_A2 + (tid - 32)] = 0.f;
    if (tid >= 64 && tid < 112)   sm[OFF_A2 + 4608 + (tid - 64)] = 0.f;

    const int Lout[6] = {65544, 32780, 16398, 8207, 4111, 2063};
    int olo[6], ohi[6];
    #pragma unroll
    for (int l = 0; l < 6; l++) {
        int c = CHK >> (l + 1);
        olo[l] = j * c;
        ohi[l] = (j == SPLIT - 1) ? Lout[l] : (j + 1) * c;
    }
    float* gd1 = orow + 65622;  float* gd2 = orow + 32842;
    float* gd3 = orow + 16444;  float* gd4 = orow + 8237;
    float* gd5 = orow + 4126;   float* gd6 = orow + 2063;

    // Async staging: s_in[buf][i] = x[pin-15+i], i in [0, 2064); zero-filled OOB.
    auto stage_async = [&](int off, int pin) {
        #pragma unroll
        for (int c = 0; c < 8; c++) {
            int i  = tid + 256 * c;
            int gi = pin - 15 + i;
            bool ok = (gi >= 0) && (gi < SIG_LEN);
            const float* gp = x + (ok ? gi : 0);
            uint32_t sa = smb + (uint32_t)(off + i) * 4u;
            int sz = ok ? 4 : 0;
            asm volatile("cp.async.ca.shared.global [%0], [%1], 4, %2;"
                         :: "r"(sa), "l"(gp), "r"(sz) : "memory");
        }
        if (tid < 16) {
            int i  = tid + 2048;
            int gi = pin - 15 + i;
            bool ok = (gi >= 0) && (gi < SIG_LEN);
            const float* gp = x + (ok ? gi : 0);
            uint32_t sa = smb + (uint32_t)(off + i) * 4u;
            int sz = ok ? 4 : 0;
            asm volatile("cp.async.ca.shared.global [%0], [%1], 4, %2;"
                         :: "r"(sa), "l"(gp), "r"(sz) : "memory");
        }
    };

    // Generic level pass: outputs q in [0, nq), 2 per thread per iter,
    // global index t = tg0 + q. Window = src[woff+2q .. woff+2q+15(+2)].
    auto level = [&](const float* __restrict__ src, int woff,
                     float* __restrict__ dst, int dst0, int dqlim,
                     float* __restrict__ det, int tg0, int lo, int hi,
                     float* __restrict__ app, int nq)
    {
        for (int q = 2 * tid; q < nq; q += 512) {
            const float* w = src + woff + 2 * q;
            ulonglong2 v0 = *(const ulonglong2*)(w);
            ulonglong2 v1 = *(const ulonglong2*)(w + 4);
            ulonglong2 v2 = *(const ulonglong2*)(w + 8);
            ulonglong2 v3 = *(const ulonglong2*)(w + 12);
            ull p8 = *(const ull*)(w + 16);
            ull P[9] = {v0.x, v0.y, v1.x, v1.y, v2.x, v2.y, v3.x, v3.y, p8};
            ull a0 = 0ull, a1 = 0ull, d0 = 0ull, d1 = 0ull;
            #pragma unroll
            for (int m = 0; m < 8; m++) {
                a0 = fma2(fa[m], P[m],     a0);
                d0 = fma2(fd[m], P[m],     d0);
                a1 = fma2(fa[m], P[m + 1], a1);
                d1 = fma2(fd[m], P[m + 1], d1);
            }
            float ra0 = hsum2(a0), ra1 = hsum2(a1);
            float rd0 = hsum2(d0), rd1 = hsum2(d1);
            if (dst) {
                if (q < dqlim)     dst[dst0 + q]     = ra0;
                if (q + 1 < dqlim) dst[dst0 + q + 1] = ra1;
            }
            const int t = tg0 + q;
            if (t >= lo && t < hi)     { det[t]     = rd0; if (app) app[t]     = ra0; }
            if (t+1 >= lo && t+1 < hi) { det[t + 1] = rd1; if (app) app[t + 1] = ra1; }
        }
    };

    const int base2 = j * 4096 - 512;            // first l2 index covered
    const int P0    = j * CHK - SS;              // scan start (left halo)
    const int nstep = (j == SPLIT - 1) ? 10 : 9;

    // Prologue: issue staging for step 0 into buffer 0
    stage_async(OFF_IN0, P0);
    asm volatile("cp.async.commit_group;" ::: "memory");

    for (int step = 0; step < nstep; step++) {
        const int pin  = P0 + step * SS;
        const int cbuf = (step & 1) ? OFF_IN1 : OFF_IN0;
        const int nbuf = (step & 1) ? OFF_IN0 : OFF_IN1;
        __syncthreads();                         // prev L1/L2 reads done

        // Carry s_l1 head <- old tail; prefetch next step; wait current.
        if (tid < 15) sm[OFF_L1 + tid] = sm[OFF_L1 + 1024 + tid];
        if (step + 1 < nstep) {
            stage_async(nbuf, pin + SS);
            asm volatile("cp.async.commit_group;" ::: "memory");
            asm volatile("cp.async.wait_group 1;" ::: "memory");
        } else {
            asm volatile("cp.async.wait_group 0;" ::: "memory");
        }
        __syncthreads();

        // Level 1: 1024 outputs at u = (pin>>1)+q; approx -> s_l1[15+q]
        level(sm + cbuf, 0, sm + OFF_L1, 15, 1 << 30,
              gd1, pin >> 1, olo[0], ohi[0], (float*)0, 1024);
        __syncthreads();

        // Level 2: 512 outputs at u2 = (pin>>2)+q; approx -> s_a2[step*512+3+q]
        level(sm + OFF_L1, 0, sm + OFF_A2, step * 512 + 3,
              Lout[1] - (base2 + step * 512),
              gd2, pin >> 2, olo[1], ohi[1], (float*)0, 512);
    }

    __syncthreads();
    // Zero tail-buffer pads (heads [0,3) and right-edge zero regions)
    if (tid < 3) { sm[OFF_L3 + tid] = 0.f; sm[OFF_L4 + tid] = 0.f; sm[OFF_L5 + tid] = 0.f; }
    if (tid >= 32 && tid < 63)  sm[OFF_L3 + 2177 + (tid - 32)] = 0.f;
    if (tid >= 64 && tid < 94)  sm[OFF_L4 + 1090 + (tid - 64)] = 0.f;
    if (tid >= 96 && tid < 126) sm[OFF_L5 +  546 + (tid - 96)] = 0.f;
    __syncthreads();

    // Tail: levels 3..6 once. Left halos 112/48/16 cover the dependency cone.
    {
        const int a3 = olo[2] - 112, n3 = ohi[2] - a3;      // even
        level(sm + OFF_A2, 276, sm + OFF_L3, 3, 1 << 30,
              gd3, a3, olo[2], ohi[2], (float*)0, n3);
        __syncthreads();

        const int a4 = olo[3] - 48, n4 = ohi[3] - a4;
        level(sm + OFF_L3, 4, sm + OFF_L4, 3, 1 << 30,
              gd4, a4, olo[3], ohi[3], (float*)0, n4);
        __syncthreads();

        const int a5 = olo[4] - 16, n5 = ohi[4] - a5;
        level(sm + OFF_L4, 4, sm + OFF_L5, 3, 1 << 30,
              gd5, a5, olo[4], ohi[4], (float*)0, n5);
        __syncthreads();

        level(sm + OFF_L5, 4, (float*)0, 0, 0,
              gd6, olo[5], olo[5], ohi[5], orow, ohi[5] - olo[5]);
    }
}

// ---------------------------------------------------------------------------
extern "C" void kernel_launch(void* const* d_in, const int* in_sizes, int n_in,
                              void* d_out, int out_size) {
    const float* signal = (const float*)d_in[0];
    const float* low    = (const float*)d_in[1];
    const float* high   = (const float*)d_in[2];
    float* out = (float*)d_out;

    constrain_kernel<<<1, 128>>>(low, high);

    dim3 grid(SPLIT, ROWS);
    fused_dwt_kernel<<<grid, 256>>>(signal, out);
}